// round 2
// baseline (speedup 1.0000x reference)
#include <cuda_runtime.h>

// ---------------------------------------------------------------------------
// FrameLevelPartFeatureExtractor — direct fp32 conv pipeline
//
// Reference pipeline (all convs followed by DOUBLE leaky_relu, slope 0.01 twice):
//   conv1: 5x5, 1->32,  H=1024 W=256, slices of 512 (halving=1), pad 2
//   conv2: 3x3, 32->32, H=1024 W=256, slices of 512, pad 1
//   maxpool 2x2
//   conv3: 3x3, 32->64, H=512 W=128, slices of 32 (halving=4), pad 1
//   conv4: 3x3, 64->64, H=512 W=128, slices of 32, pad 1
//   maxpool 2x2
//   conv5: 3x3, 64->128,  H=256 W=64, slices of 1 (halving=8) -> 1x3 (mid row)
//   conv6: 3x3, 128->128, H=256 W=64, slices of 1            -> 1x3 (mid row)
// Output: [2,128,256,64] fp32
// ---------------------------------------------------------------------------

// Ping-pong scratch (max intermediate: 2*32*1024*256 = 16,777,216 floats)
__device__ float g_bufA[16777216];
__device__ float g_bufB[16777216];

__device__ __forceinline__ float dlrelu(float v) {
    // leaky_relu applied twice: negatives get 0.01 * 0.01
    return v > 0.0f ? v : 0.01f * (0.01f * v);
}

// ---------------------------------------------------------------------------
// conv1: 5x5, Cin=1, Cout=32, H=1024, W=256, sliceH=512
// Block: 256 threads -> tile 32 oc x 4 h x 64 w.
// Thread: 8 oc x 4 w accumulators at one row.
// ---------------------------------------------------------------------------
__global__ __launch_bounds__(256, 2)
void conv5x5_c1(const float* __restrict__ in, const float* __restrict__ wgt,
                float* __restrict__ out)
{
    const int H = 1024, W = 256, SL = 512, TH = 4, TW = 64;
    const int n  = blockIdx.z;
    const int h0 = blockIdx.y * TH;
    const int w0 = blockIdx.x * TW;
    const int tid = threadIdx.x;
    const int ocb = (tid & 3) * 8;          // oc base: 0,8,16,24
    const int lw  = ((tid >> 2) & 15) * 4;  // local w base: 0..60
    const int hh  = tid >> 6;               // local h: 0..3

    __shared__ float si[TH + 4][TW + 4];    // 8 x 68
    __shared__ float sw[32 * 25];

    for (int i = tid; i < 32 * 25; i += 256) sw[i] = wgt[i];

    const int ss = (h0 / SL) * SL, se = ss + SL;
    for (int i = tid; i < (TH + 4) * (TW + 4); i += 256) {
        int r = i / (TW + 4), c = i % (TW + 4);
        int g = h0 - 2 + r, gc = w0 - 2 + c;
        float v = 0.0f;
        if (g >= ss && g < se && gc >= 0 && gc < W)
            v = in[(n * H + g) * W + gc];   // Cin = 1
        si[r][c] = v;
    }
    __syncthreads();

    float iv[5][8];
#pragma unroll
    for (int r = 0; r < 5; r++)
#pragma unroll
        for (int c = 0; c < 8; c++)
            iv[r][c] = si[hh + r][lw + c];

    float acc[8][4];
#pragma unroll
    for (int o = 0; o < 8; o++)
#pragma unroll
        for (int x = 0; x < 4; x++) acc[o][x] = 0.0f;

#pragma unroll
    for (int o = 0; o < 8; o++) {
        const float* wp = &sw[(ocb + o) * 25];
#pragma unroll
        for (int r = 0; r < 5; r++)
#pragma unroll
            for (int kc = 0; kc < 5; kc++) {
                float wv = wp[r * 5 + kc];
#pragma unroll
                for (int x = 0; x < 4; x++)
                    acc[o][x] += iv[r][kc + x] * wv;
            }
    }

#pragma unroll
    for (int o = 0; o < 8; o++) {
        float4 v;
        v.x = dlrelu(acc[o][0]); v.y = dlrelu(acc[o][1]);
        v.z = dlrelu(acc[o][2]); v.w = dlrelu(acc[o][3]);
        int oc = ocb + o;
        *reinterpret_cast<float4*>(
            &out[(((n * 32) + oc) * H + h0 + hh) * W + w0 + lw]) = v;
    }
}

// ---------------------------------------------------------------------------
// Generic 3x3 focal conv. ONEROW=1 means sliceH==1: degenerate 1x3 using the
// middle kernel row only (vertical taps always hit slice padding).
// Block: 256 threads -> 32 oc x 4 h x 64 w tile; cin chunked by 8.
// Thread mapping: 4 oc x 8 w (reduces LDS per FFMA vs 8x4).
// Grid: (W/64, H/4, N * Cout/32)
// ---------------------------------------------------------------------------
template <int CIN, int ONEROW>
__global__ __launch_bounds__(256, 2)
void conv3x3_k(const float* __restrict__ in, const float* __restrict__ wgt,
               float* __restrict__ out, int H, int W, int sliceH, int OCG)
{
    const int TH = 4, TW = 64, CC = 8;
    const int z   = blockIdx.z;
    const int ocg = z % OCG;
    const int n   = z / OCG;
    const int Cout = OCG * 32;
    const int h0 = blockIdx.y * TH;
    const int w0 = blockIdx.x * TW;
    const int tid = threadIdx.x;
    const int ocb = (tid & 7) * 4;          // oc base: 0,4,...,28
    const int lw  = ((tid >> 3) & 7) * 8;   // local w base: 0..56
    const int hh  = tid >> 6;               // local h: 0..3

    __shared__ float si[CC][TH + 2][TW + 2];   // 8 x 6 x 66
    __shared__ float sw[32][CC * 9 + 1];       // padded stride 73 (bank spread)

    const int ss = (h0 / sliceH) * sliceH, se = ss + sliceH;

    float acc[4][8];
#pragma unroll
    for (int o = 0; o < 4; o++)
#pragma unroll
        for (int x = 0; x < 8; x++) acc[o][x] = 0.0f;

    for (int c0 = 0; c0 < CIN; c0 += CC) {
        // ---- stage input chunk ----
        const int TOT = CC * (TH + 2) * (TW + 2);
        for (int i = tid; i < TOT; i += 256) {
            int c   = i / ((TH + 2) * (TW + 2));
            int rem = i % ((TH + 2) * (TW + 2));
            int r   = rem / (TW + 2);
            int col = rem % (TW + 2);
            int g = h0 - 1 + r, gc = w0 - 1 + col;
            bool okr = ONEROW ? (g >= 0 && g < H) : (g >= ss && g < se);
            float v = 0.0f;
            if (okr && gc >= 0 && gc < W)
                v = in[((n * CIN + c0 + c) * H + g) * W + gc];
            si[c][r][col] = v;
        }
        // ---- stage weights: global layout [Cout][CIN][3][3] ----
        for (int i = tid; i < 32 * CC * 9; i += 256) {
            int o   = i / (CC * 9);
            int rem = i % (CC * 9);
            sw[o][rem] = wgt[((ocg * 32 + o) * CIN + c0 + rem / 9) * 9 + rem % 9];
        }
        __syncthreads();

#pragma unroll
        for (int c = 0; c < CC; c++) {
            if (ONEROW) {
                float iv[10];
#pragma unroll
                for (int x = 0; x < 10; x++) iv[x] = si[c][hh + 1][lw + x];
#pragma unroll
                for (int o = 0; o < 4; o++) {
#pragma unroll
                    for (int kc = 0; kc < 3; kc++) {
                        float wv = sw[ocb + o][c * 9 + 3 + kc];  // middle row
#pragma unroll
                        for (int x = 0; x < 8; x++)
                            acc[o][x] += iv[kc + x] * wv;
                    }
                }
            } else {
                float iv[3][10];
#pragma unroll
                for (int r = 0; r < 3; r++)
#pragma unroll
                    for (int x = 0; x < 10; x++)
                        iv[r][x] = si[c][hh + r][lw + x];
#pragma unroll
                for (int o = 0; o < 4; o++) {
#pragma unroll
                    for (int r = 0; r < 3; r++)
#pragma unroll
                        for (int kc = 0; kc < 3; kc++) {
                            float wv = sw[ocb + o][c * 9 + r * 3 + kc];
#pragma unroll
                            for (int x = 0; x < 8; x++)
                                acc[o][x] += iv[r][kc + x] * wv;
                        }
                }
            }
        }
        __syncthreads();
    }

#pragma unroll
    for (int o = 0; o < 4; o++) {
        int oc = ocg * 32 + ocb + o;
        float* op = &out[((n * Cout + oc) * H + h0 + hh) * W + w0 + lw];
        float4 v0, v1;
        v0.x = dlrelu(acc[o][0]); v0.y = dlrelu(acc[o][1]);
        v0.z = dlrelu(acc[o][2]); v0.w = dlrelu(acc[o][3]);
        v1.x = dlrelu(acc[o][4]); v1.y = dlrelu(acc[o][5]);
        v1.z = dlrelu(acc[o][6]); v1.w = dlrelu(acc[o][7]);
        *reinterpret_cast<float4*>(op)     = v0;
        *reinterpret_cast<float4*>(op + 4) = v1;
    }
}

// ---------------------------------------------------------------------------
// 2x2 max pool, stride 2. Channels folded: NC = N*C.
// ---------------------------------------------------------------------------
__global__ void maxpool2_k(const float* __restrict__ in, float* __restrict__ out,
                           int NC, int H, int W)
{
    int HO = H >> 1, WO = W >> 1;
    int total = NC * HO * WO;
    int idx = blockIdx.x * blockDim.x + threadIdx.x;
    if (idx >= total) return;
    int wo = idx % WO;
    int t  = idx / WO;
    int ho = t % HO;
    int ch = t / HO;
    const float* p = in + ((long)ch * H + 2 * ho) * W + 2 * wo;
    out[idx] = fmaxf(fmaxf(p[0], p[1]), fmaxf(p[W], p[W + 1]));
}

// ---------------------------------------------------------------------------
extern "C" void kernel_launch(void* const* d_in, const int* in_sizes, int n_in,
                              void* d_out, int out_size)
{
    const float* x  = (const float*)d_in[0];
    const float* w1 = (const float*)d_in[1];
    const float* w2 = (const float*)d_in[2];
    const float* w3 = (const float*)d_in[3];
    const float* w4 = (const float*)d_in[4];
    const float* w5 = (const float*)d_in[5];
    const float* w6 = (const float*)d_in[6];
    float* out = (float*)d_out;

    float *A, *B;
    cudaGetSymbolAddress((void**)&A, g_bufA);
    cudaGetSymbolAddress((void**)&B, g_bufB);

    // conv1: x [2,1,1024,256] -> A [2,32,1024,256]
    conv5x5_c1<<<dim3(256 / 64, 1024 / 4, 2), 256>>>(x, w1, A);

    // conv2: A -> B [2,32,1024,256]  (sliceH=512)
    conv3x3_k<32, 0><<<dim3(256 / 64, 1024 / 4, 2 * 1), 256>>>(A, w2, B, 1024, 256, 512, 1);

    // pool1: B -> A [2,32,512,128]
    {
        int NC = 2 * 32, H = 1024, W = 256;
        int total = NC * (H / 2) * (W / 2);
        maxpool2_k<<<(total + 255) / 256, 256>>>(B, A, NC, H, W);
    }

    // conv3: A -> B [2,64,512,128]  (sliceH=32)
    conv3x3_k<32, 0><<<dim3(128 / 64, 512 / 4, 2 * 2), 256>>>(A, w3, B, 512, 128, 32, 2);

    // conv4: B -> A [2,64,512,128]
    conv3x3_k<64, 0><<<dim3(128 / 64, 512 / 4, 2 * 2), 256>>>(B, w4, A, 512, 128, 32, 2);

    // pool2: A -> B [2,64,256,64]
    {
        int NC = 2 * 64, H = 512, W = 128;
        int total = NC * (H / 2) * (W / 2);
        maxpool2_k<<<(total + 255) / 256, 256>>>(A, B, NC, H, W);
    }

    // conv5: B -> A [2,128,256,64]  (sliceH=1 -> 1x3 middle row)
    conv3x3_k<64, 1><<<dim3(64 / 64, 256 / 4, 2 * 4), 256>>>(B, w5, A, 256, 64, 1, 4);

    // conv6: A -> out [2,128,256,64]
    conv3x3_k<128, 1><<<dim3(64 / 64, 256 / 4, 2 * 4), 256>>>(A, w6, out, 256, 64, 1, 4);
}

// round 3
// speedup vs baseline: 1.3413x; 1.3413x over previous
#include <cuda_runtime.h>

// ---------------------------------------------------------------------------
// FrameLevelPartFeatureExtractor — direct fp32 conv pipeline, cp.async
// double-buffered, staging index math hoisted out of the cin-chunk loop.
//
//   conv1: 5x5, 1->32,  H=1024 W=256, sliceH=512, pad 2
//   conv2: 3x3, 32->32, H=1024 W=256, sliceH=512, pad 1
//   maxpool 2x2
//   conv3: 3x3, 32->64, H=512 W=128, sliceH=32, pad 1
//   conv4: 3x3, 64->64, H=512 W=128, sliceH=32, pad 1
//   maxpool 2x2
//   conv5: 3x3->1x3, 64->128,  H=256 W=64 (sliceH=1: middle row only)
//   conv6: 3x3->1x3, 128->128, H=256 W=64
// All convs followed by DOUBLE leaky_relu (0.01 twice).
// Output: [2,128,256,64] fp32
// ---------------------------------------------------------------------------

__device__ float g_bufA[16777216];
__device__ float g_bufB[16777216];

__device__ __forceinline__ float dlrelu(float v) {
    return v > 0.0f ? v : 0.01f * (0.01f * v);
}

__device__ __forceinline__ void cp4(unsigned dst, const void* src, int sz) {
    asm volatile("cp.async.ca.shared.global [%0], [%1], 4, %2;\n"
                 :: "r"(dst), "l"(src), "r"(sz));
}
__device__ __forceinline__ void cp_commit() {
    asm volatile("cp.async.commit_group;\n" ::);
}

// ---------------------------------------------------------------------------
// conv1: 5x5, Cin=1, Cout=32. Block: 256 thr -> 32 oc x 4 h x 64 w tile.
// ---------------------------------------------------------------------------
__global__ __launch_bounds__(256, 2)
void conv5x5_c1(const float* __restrict__ in, const float* __restrict__ wgt,
                float* __restrict__ out)
{
    const int H = 1024, W = 256, SL = 512, TH = 4, TW = 64;
    const int n  = blockIdx.z;
    const int h0 = blockIdx.y * TH;
    const int w0 = blockIdx.x * TW;
    const int tid = threadIdx.x;
    const int ocb = (tid & 3) * 8;
    const int lw  = ((tid >> 2) & 15) * 4;
    const int hh  = tid >> 6;

    __shared__ float si[TH + 4][TW + 4];
    __shared__ float sw[32 * 25];

    for (int i = tid; i < 32 * 25; i += 256) sw[i] = wgt[i];

    const int ss = (h0 / SL) * SL, se = ss + SL;
    for (int i = tid; i < (TH + 4) * (TW + 4); i += 256) {
        int r = i / (TW + 4), c = i % (TW + 4);
        int g = h0 - 2 + r, gc = w0 - 2 + c;
        float v = 0.0f;
        if (g >= ss && g < se && gc >= 0 && gc < W)
            v = in[(n * H + g) * W + gc];
        si[r][c] = v;
    }
    __syncthreads();

    float iv[5][8];
#pragma unroll
    for (int r = 0; r < 5; r++)
#pragma unroll
        for (int c = 0; c < 8; c++)
            iv[r][c] = si[hh + r][lw + c];

    float acc[8][4];
#pragma unroll
    for (int o = 0; o < 8; o++)
#pragma unroll
        for (int x = 0; x < 4; x++) acc[o][x] = 0.0f;

#pragma unroll
    for (int o = 0; o < 8; o++) {
        const float* wp = &sw[(ocb + o) * 25];
#pragma unroll
        for (int r = 0; r < 5; r++)
#pragma unroll
            for (int kc = 0; kc < 5; kc++) {
                float wv = wp[r * 5 + kc];
#pragma unroll
                for (int x = 0; x < 4; x++)
                    acc[o][x] += iv[r][kc + x] * wv;
            }
    }

#pragma unroll
    for (int o = 0; o < 8; o++) {
        float4 v;
        v.x = dlrelu(acc[o][0]); v.y = dlrelu(acc[o][1]);
        v.z = dlrelu(acc[o][2]); v.w = dlrelu(acc[o][3]);
        int oc = ocb + o;
        *reinterpret_cast<float4*>(
            &out[(((n * 32) + oc) * H + h0 + hh) * W + w0 + lw]) = v;
    }
}

// ---------------------------------------------------------------------------
// Generic 3x3 focal conv, cp.async double-buffered.
// ONEROW=1 (sliceH==1): 1x3 with middle weight row; stage 4 rows, no v-halo.
// Block: 256 thr -> 32 oc x 4 h x 64 w tile; thread: 4 oc x 8 w.
// Grid: (W/64, H/4, N * Cout/32)
// ---------------------------------------------------------------------------
template <int CIN, int ONEROW>
__global__ __launch_bounds__(256, 2)
void conv3x3_k(const float* __restrict__ in, const float* __restrict__ wgt,
               float* __restrict__ out, int H, int W, int sliceH, int OCG)
{
    const int TH = 4, CC = 8;
    const int ROWS = ONEROW ? TH : (TH + 2);      // staged rows
    const int KW   = ONEROW ? 3 : 9;              // weights per (oc,cin)
    const int SI_TOT = CC * ROWS * 66;
    const int SI_NITER = (SI_TOT + 255) / 256;
    const int SW_TOT = 32 * CC * KW;
    const int SW_NITER = (SW_TOT + 255) / 256;
    const int WST = CC * KW + 1;                  // padded weight stride
    const int NCH = CIN / CC;

    __shared__ float si[2][SI_TOT];
    __shared__ float sw[2][32 * WST];

    const int z   = blockIdx.z;
    const int ocg = z % OCG;
    const int n   = z / OCG;
    const int Cout = OCG * 32;
    const int h0 = blockIdx.y * TH;
    const int w0 = blockIdx.x * 64;
    const int tid = threadIdx.x;
    const int ocb = (tid & 7) * 4;
    const int lw  = ((tid >> 3) & 7) * 8;
    const int hh  = tid >> 6;

    const int ss = ONEROW ? 0 : (h0 / sliceH) * sliceH;
    const int se = ss + sliceH;

    const float* base = in + (size_t)n * CIN * H * W;
    const float* wgt0 = wgt + (size_t)(ocg * 32) * CIN * 9;

    // --- hoisted staging descriptors (chunk-invariant) ---
    int si_off[SI_NITER];   // -1: skip, -2: zero-fill, else gmem offset (chunk 0)
#pragma unroll
    for (int k = 0; k < SI_NITER; k++) {
        int i = tid + k * 256;
        int off = -1;
        if (i < SI_TOT) {
            int c   = i / (ROWS * 66);
            int rem = i - c * (ROWS * 66);
            int r   = rem / 66;
            int col = rem - r * 66;
            int g  = ONEROW ? (h0 + r) : (h0 - 1 + r);
            int gc = w0 - 1 + col;
            bool ok = (gc >= 0) && (gc < W);
            if (!ONEROW) ok = ok && (g >= ss) && (g < se);
            off = ok ? ((c * H + g) * W + gc) : -2;
        }
        si_off[k] = off;
    }
    int sw_desc[SW_NITER];  // gmem offset (24b) | o (8b); -1: skip
#pragma unroll
    for (int k = 0; k < SW_NITER; k++) {
        int i = tid + k * 256;
        int d = -1;
        if (i < SW_TOT) {
            int o   = i / (CC * KW);
            int rem = i - o * (CC * KW);
            int c = rem / KW;
            int j = rem - c * KW;
            int jj = ONEROW ? (j + 3) : j;     // middle weight row for 1x3
            int goff = (o * CIN + c) * 9 + jj;
            d = goff | (o << 24);
        }
        sw_desc[k] = d;
    }

    unsigned si_s[2], sw_s[2];
    si_s[0] = (unsigned)__cvta_generic_to_shared(&si[0][0]);
    si_s[1] = (unsigned)__cvta_generic_to_shared(&si[1][0]);
    sw_s[0] = (unsigned)__cvta_generic_to_shared(&sw[0][0]);
    sw_s[1] = (unsigned)__cvta_generic_to_shared(&sw[1][0]);

    auto stage = [&](int t, int buf) {
        const float* cbase = base + (size_t)(t * CC) * H * W;
#pragma unroll
        for (int k = 0; k < SI_NITER; k++) {
            int off = si_off[k];
            if (off != -1) {
                cp4(si_s[buf] + (unsigned)(tid + k * 256) * 4,
                    off >= 0 ? (const void*)(cbase + off) : (const void*)cbase,
                    off >= 0 ? 4 : 0);
            }
        }
        const float* wbase = wgt0 + t * CC * 9;
#pragma unroll
        for (int k = 0; k < SW_NITER; k++) {
            int d = sw_desc[k];
            if (d >= 0) {
                int o = d >> 24;
                int goff = d & 0xFFFFFF;
                int i = tid + k * 256;
                // padded flat index = i + o  (since pad = +1 word per oc row)
                cp4(sw_s[buf] + (unsigned)(i + o) * 4, wbase + goff, 4);
            }
        }
        cp_commit();
    };

    float acc[4][8];
#pragma unroll
    for (int o = 0; o < 4; o++)
#pragma unroll
        for (int x = 0; x < 8; x++) acc[o][x] = 0.0f;

    stage(0, 0);

    for (int t = 0; t < NCH; t++) {
        int buf = t & 1;
        if (t + 1 < NCH) {
            stage(t + 1, buf ^ 1);
            asm volatile("cp.async.wait_group 1;\n" ::);
        } else {
            asm volatile("cp.async.wait_group 0;\n" ::);
        }
        __syncthreads();

        const float* sib = si[buf];
        const float* swb = sw[buf];
#pragma unroll
        for (int c = 0; c < CC; c++) {
            if (ONEROW) {
                float iv[10];
                const float* rp = sib + (c * ROWS + hh) * 66 + lw;
#pragma unroll
                for (int x = 0; x < 10; x++) iv[x] = rp[x];
#pragma unroll
                for (int o = 0; o < 4; o++) {
                    const float* wp = swb + (ocb + o) * WST + c * KW;
#pragma unroll
                    for (int q = 0; q < 3; q++) {
                        float wv = wp[q];
#pragma unroll
                        for (int x = 0; x < 8; x++)
                            acc[o][x] += iv[q + x] * wv;
                    }
                }
            } else {
                float iv[3][10];
#pragma unroll
                for (int r = 0; r < 3; r++) {
                    const float* rp = sib + (c * ROWS + hh + r) * 66 + lw;
#pragma unroll
                    for (int x = 0; x < 10; x++) iv[r][x] = rp[x];
                }
#pragma unroll
                for (int o = 0; o < 4; o++) {
                    const float* wp = swb + (ocb + o) * WST + c * KW;
#pragma unroll
                    for (int r = 0; r < 3; r++)
#pragma unroll
                        for (int q = 0; q < 3; q++) {
                            float wv = wp[r * 3 + q];
#pragma unroll
                            for (int x = 0; x < 8; x++)
                                acc[o][x] += iv[r][q + x] * wv;
                        }
                }
            }
        }
        __syncthreads();   // protect buf before it is re-staged next iter
    }

#pragma unroll
    for (int o = 0; o < 4; o++) {
        int oc = ocg * 32 + ocb + o;
        float* op = &out[((size_t)(n * Cout + oc) * H + h0 + hh) * W + w0 + lw];
        float4 v0, v1;
        v0.x = dlrelu(acc[o][0]); v0.y = dlrelu(acc[o][1]);
        v0.z = dlrelu(acc[o][2]); v0.w = dlrelu(acc[o][3]);
        v1.x = dlrelu(acc[o][4]); v1.y = dlrelu(acc[o][5]);
        v1.z = dlrelu(acc[o][6]); v1.w = dlrelu(acc[o][7]);
        *reinterpret_cast<float4*>(op)     = v0;
        *reinterpret_cast<float4*>(op + 4) = v1;
    }
}

// ---------------------------------------------------------------------------
// 2x2 max pool, stride 2.
// ---------------------------------------------------------------------------
__global__ void maxpool2_k(const float* __restrict__ in, float* __restrict__ out,
                           int NC, int H, int W)
{
    int HO = H >> 1, WO = W >> 1;
    int total = NC * HO * WO;
    int idx = blockIdx.x * blockDim.x + threadIdx.x;
    if (idx >= total) return;
    int wo = idx % WO;
    int t  = idx / WO;
    int ho = t % HO;
    int ch = t / HO;
    const float* p = in + ((long)ch * H + 2 * ho) * W + 2 * wo;
    out[idx] = fmaxf(fmaxf(p[0], p[1]), fmaxf(p[W], p[W + 1]));
}

// ---------------------------------------------------------------------------
extern "C" void kernel_launch(void* const* d_in, const int* in_sizes, int n_in,
                              void* d_out, int out_size)
{
    const float* x  = (const float*)d_in[0];
    const float* w1 = (const float*)d_in[1];
    const float* w2 = (const float*)d_in[2];
    const float* w3 = (const float*)d_in[3];
    const float* w4 = (const float*)d_in[4];
    const float* w5 = (const float*)d_in[5];
    const float* w6 = (const float*)d_in[6];
    float* out = (float*)d_out;

    float *A, *B;
    cudaGetSymbolAddress((void**)&A, g_bufA);
    cudaGetSymbolAddress((void**)&B, g_bufB);

    // conv1: x [2,1,1024,256] -> A [2,32,1024,256]
    conv5x5_c1<<<dim3(4, 256, 2), 256>>>(x, w1, A);

    // conv2: A -> B (sliceH=512)
    conv3x3_k<32, 0><<<dim3(4, 256, 2), 256>>>(A, w2, B, 1024, 256, 512, 1);

    // pool1: B -> A [2,32,512,128]
    {
        int total = 64 * 512 * 128;
        maxpool2_k<<<(total + 255) / 256, 256>>>(B, A, 64, 1024, 256);
    }

    // conv3: A -> B [2,64,512,128] (sliceH=32)
    conv3x3_k<32, 0><<<dim3(2, 128, 4), 256>>>(A, w3, B, 512, 128, 32, 2);

    // conv4: B -> A
    conv3x3_k<64, 0><<<dim3(2, 128, 4), 256>>>(B, w4, A, 512, 128, 32, 2);

    // pool2: A -> B [2,64,256,64]
    {
        int total = 128 * 256 * 64;
        maxpool2_k<<<(total + 255) / 256, 256>>>(A, B, 128, 512, 128);
    }

    // conv5: B -> A [2,128,256,64] (1x3 middle row)
    conv3x3_k<64, 1><<<dim3(1, 64, 8), 256>>>(B, w5, A, 256, 64, 1, 4);

    // conv6: A -> out
    conv3x3_k<128, 1><<<dim3(1, 64, 8), 256>>>(A, w6, out, 256, 64, 1, 4);
}

// round 4
// speedup vs baseline: 1.4618x; 1.0899x over previous
#include <cuda_runtime.h>

// ---------------------------------------------------------------------------
// FrameLevelPartFeatureExtractor — fp32 conv pipeline using packed f32x2 FMA
// (FFMA2) for all 3x3 layers. Accumulators paired over adjacent output
// channels; weights pre-paired in smem; cp.async double-buffered staging
// with hoisted descriptors.
// ---------------------------------------------------------------------------

typedef unsigned long long u64;

__device__ float g_bufA[16777216];
__device__ float g_bufB[16777216];

__device__ __forceinline__ float dlrelu(float v) {
    return v > 0.0f ? v : 0.01f * (0.01f * v);
}

__device__ __forceinline__ void cp4(unsigned dst, const void* src, int sz) {
    asm volatile("cp.async.ca.shared.global [%0], [%1], 4, %2;\n"
                 :: "r"(dst), "l"(src), "r"(sz));
}
__device__ __forceinline__ void cp_commit() {
    asm volatile("cp.async.commit_group;\n" ::);
}

__device__ __forceinline__ u64 dup_f(float v) {
    u64 r; asm("mov.b64 %0, {%1, %1};" : "=l"(r) : "f"(v)); return r;
}
__device__ __forceinline__ void ffma2(u64& d, u64 a, u64 b) {
    asm("fma.rn.f32x2 %0, %1, %2, %0;" : "+l"(d) : "l"(a), "l"(b));
}
__device__ __forceinline__ float2 unpk(u64 a) {
    float2 f; asm("mov.b64 {%0, %1}, %2;" : "=f"(f.x), "=f"(f.y) : "l"(a));
    return f;
}

// ---------------------------------------------------------------------------
// conv1: 5x5, Cin=1, Cout=32 (small layer; scalar path).
// ---------------------------------------------------------------------------
__global__ __launch_bounds__(256, 2)
void conv5x5_c1(const float* __restrict__ in, const float* __restrict__ wgt,
                float* __restrict__ out)
{
    const int H = 1024, W = 256, SL = 512, TH = 4, TW = 64;
    const int n  = blockIdx.z;
    const int h0 = blockIdx.y * TH;
    const int w0 = blockIdx.x * TW;
    const int tid = threadIdx.x;
    const int ocb = (tid & 3) * 8;
    const int lw  = ((tid >> 2) & 15) * 4;
    const int hh  = tid >> 6;

    __shared__ float si[TH + 4][TW + 4];
    __shared__ float sw[32 * 25];

    for (int i = tid; i < 32 * 25; i += 256) sw[i] = wgt[i];

    const int ss = (h0 / SL) * SL, se = ss + SL;
    for (int i = tid; i < (TH + 4) * (TW + 4); i += 256) {
        int r = i / (TW + 4), c = i % (TW + 4);
        int g = h0 - 2 + r, gc = w0 - 2 + c;
        float v = 0.0f;
        if (g >= ss && g < se && gc >= 0 && gc < W)
            v = in[(n * H + g) * W + gc];
        si[r][c] = v;
    }
    __syncthreads();

    float iv[5][8];
#pragma unroll
    for (int r = 0; r < 5; r++)
#pragma unroll
        for (int c = 0; c < 8; c++)
            iv[r][c] = si[hh + r][lw + c];

    float acc[8][4];
#pragma unroll
    for (int o = 0; o < 8; o++)
#pragma unroll
        for (int x = 0; x < 4; x++) acc[o][x] = 0.0f;

#pragma unroll
    for (int o = 0; o < 8; o++) {
        const float* wp = &sw[(ocb + o) * 25];
#pragma unroll
        for (int r = 0; r < 5; r++)
#pragma unroll
            for (int kc = 0; kc < 5; kc++) {
                float wv = wp[r * 5 + kc];
#pragma unroll
                for (int x = 0; x < 4; x++)
                    acc[o][x] += iv[r][kc + x] * wv;
            }
    }

#pragma unroll
    for (int o = 0; o < 8; o++) {
        float4 v;
        v.x = dlrelu(acc[o][0]); v.y = dlrelu(acc[o][1]);
        v.z = dlrelu(acc[o][2]); v.w = dlrelu(acc[o][3]);
        int oc = ocb + o;
        *reinterpret_cast<float4*>(
            &out[(((n * 32) + oc) * H + h0 + hh) * W + w0 + lw]) = v;
    }
}

// ---------------------------------------------------------------------------
// 3x3 focal conv with f32x2 packed FMA. ONEROW=1: 1x3 (middle weight row).
// Block 256 thr -> 32 oc x 4 h x 64 w tile. Thread: 2 oc-pairs x 8 w.
// Weights staged PRE-PAIRED over adjacent oc: swp[c][o2(16)][KW] as u64.
// ---------------------------------------------------------------------------
template <int CIN, int ONEROW>
__global__ __launch_bounds__(256, 2)
void conv3x3_f2(const float* __restrict__ in, const float* __restrict__ wgt,
                float* __restrict__ out, int H, int W, int sliceH, int OCG)
{
    const int TH = 4, CC = 8;
    const int ROWS = ONEROW ? TH : (TH + 2);
    const int KW   = ONEROW ? 3 : 9;
    const int SI_TOT = CC * ROWS * 66;
    const int SI_NITER = (SI_TOT + 255) / 256;
    const int SW_TOT = 32 * CC * KW;
    const int SW_NITER = (SW_TOT + 255) / 256;
    const int NCH = CIN / CC;

    __shared__ float si[2][SI_TOT];
    __shared__ u64   swp[2][CC * 16 * KW];    // paired weights

    const int z   = blockIdx.z;
    const int ocg = z % OCG;
    const int n   = z / OCG;
    const int Cout = OCG * 32;
    const int h0 = blockIdx.y * TH;
    const int w0 = blockIdx.x * 64;
    const int tid = threadIdx.x;
    const int ocb = (tid & 7) * 4;          // 4 consecutive oc per thread
    const int op0 = (tid & 7) * 2;          // first oc-pair index (of 16)
    const int lw  = ((tid >> 3) & 7) * 8;
    const int hh  = tid >> 6;

    const int ss = ONEROW ? 0 : (h0 / sliceH) * sliceH;
    const int se = ss + sliceH;

    const float* base = in + (size_t)n * CIN * H * W;
    const float* wgt0 = wgt + (size_t)(ocg * 32) * CIN * 9;

    // ---- hoisted input staging descriptors ----
    int si_off[SI_NITER];   // -1 skip, -2 zero-fill, else gmem offset (chunk 0)
#pragma unroll
    for (int k = 0; k < SI_NITER; k++) {
        int i = tid + k * 256;
        int off = -1;
        if (i < SI_TOT) {
            int c   = i / (ROWS * 66);
            int rem = i - c * (ROWS * 66);
            int r   = rem / 66;
            int col = rem - r * 66;
            int g  = ONEROW ? (h0 + r) : (h0 - 1 + r);
            int gc = w0 - 1 + col;
            bool ok = (gc >= 0) && (gc < W);
            if (!ONEROW) ok = ok && (g >= ss) && (g < se);
            off = ok ? ((c * H + g) * W + gc) : -2;
        }
        si_off[k] = off;
    }
    // ---- hoisted weight staging descriptors (paired layout) ----
    int sw_src[SW_NITER], sw_dst[SW_NITER];
#pragma unroll
    for (int k = 0; k < SW_NITER; k++) {
        int i = tid + k * 256;
        int s = -1, d = 0;
        if (i < SW_TOT) {
            int o   = i / (CC * KW);
            int rem = i - o * (CC * KW);
            int c = rem / KW;
            int j = rem - c * KW;
            int jj = ONEROW ? (j + 3) : j;            // middle weight row
            s = (o * CIN + c) * 9 + jj;
            d = ((c * 16 + (o >> 1)) * KW + j) * 8 + (o & 1) * 4;
        }
        sw_src[k] = s; sw_dst[k] = d;
    }

    unsigned si_s[2], sw_s[2];
    si_s[0] = (unsigned)__cvta_generic_to_shared(&si[0][0]);
    si_s[1] = (unsigned)__cvta_generic_to_shared(&si[1][0]);
    sw_s[0] = (unsigned)__cvta_generic_to_shared(&swp[0][0]);
    sw_s[1] = (unsigned)__cvta_generic_to_shared(&swp[1][0]);

    auto stage = [&](int t, int buf) {
        const float* cbase = base + (size_t)(t * CC) * H * W;
#pragma unroll
        for (int k = 0; k < SI_NITER; k++) {
            int off = si_off[k];
            if (off != -1) {
                cp4(si_s[buf] + (unsigned)(tid + k * 256) * 4,
                    off >= 0 ? (const void*)(cbase + off) : (const void*)cbase,
                    off >= 0 ? 4 : 0);
            }
        }
        const float* wbase = wgt0 + t * CC * 9;
#pragma unroll
        for (int k = 0; k < SW_NITER; k++) {
            int s = sw_src[k];
            if (s >= 0)
                cp4(sw_s[buf] + (unsigned)sw_dst[k], wbase + s, 4);
        }
        cp_commit();
    };

    u64 acc[2][8];
#pragma unroll
    for (int p = 0; p < 2; p++)
#pragma unroll
        for (int x = 0; x < 8; x++) acc[p][x] = 0ULL;

    stage(0, 0);

    for (int t = 0; t < NCH; t++) {
        int buf = t & 1;
        if (t + 1 < NCH) {
            stage(t + 1, buf ^ 1);
            asm volatile("cp.async.wait_group 1;\n" ::);
        } else {
            asm volatile("cp.async.wait_group 0;\n" ::);
        }
        __syncthreads();

        const float* sib = si[buf];
        const u64*   swb = swp[buf];
#pragma unroll
        for (int c = 0; c < CC; c++) {
#pragma unroll
            for (int r = 0; r < (ONEROW ? 1 : 3); r++) {
                const float* rp = sib + (c * ROWS + hh + r) * 66 + lw;
                u64 dup[10];
#pragma unroll
                for (int k = 0; k < 10; k++) dup[k] = dup_f(rp[k]);
#pragma unroll
                for (int p = 0; p < 2; p++) {
                    const u64* wp = swb + (c * 16 + op0 + p) * KW
                                        + (ONEROW ? 0 : r * 3);
#pragma unroll
                    for (int q = 0; q < 3; q++) {
                        u64 wv = wp[q];
#pragma unroll
                        for (int x = 0; x < 8; x++)
                            ffma2(acc[p][x], dup[q + x], wv);
                    }
                }
            }
        }
        __syncthreads();   // protect buf before next restage
    }

#pragma unroll
    for (int p = 0; p < 2; p++) {
        float lo[8], hi[8];
#pragma unroll
        for (int x = 0; x < 8; x++) {
            float2 f = unpk(acc[p][x]);
            lo[x] = dlrelu(f.x);
            hi[x] = dlrelu(f.y);
        }
        int oc0 = ocg * 32 + ocb + 2 * p;
        float* o0 = out + ((size_t)(n * Cout + oc0) * H + h0 + hh) * W + w0 + lw;
        float* o1 = o0 + (size_t)H * W;
        *reinterpret_cast<float4*>(o0)     = make_float4(lo[0], lo[1], lo[2], lo[3]);
        *reinterpret_cast<float4*>(o0 + 4) = make_float4(lo[4], lo[5], lo[6], lo[7]);
        *reinterpret_cast<float4*>(o1)     = make_float4(hi[0], hi[1], hi[2], hi[3]);
        *reinterpret_cast<float4*>(o1 + 4) = make_float4(hi[4], hi[5], hi[6], hi[7]);
    }
}

// ---------------------------------------------------------------------------
// 2x2 max pool, stride 2, 2 outputs per thread (float4 in, float2 out).
// ---------------------------------------------------------------------------
__global__ void maxpool2_k(const float* __restrict__ in, float* __restrict__ out,
                           int NC, int H, int W)
{
    int HO = H >> 1, WO = W >> 1, WO2 = WO >> 1;
    int total = NC * HO * WO2;
    int idx = blockIdx.x * blockDim.x + threadIdx.x;
    if (idx >= total) return;
    int wo2 = idx % WO2;
    int t   = idx / WO2;
    int ho  = t % HO;
    int ch  = t / HO;
    const float* p = in + ((long)ch * H + 2 * ho) * W + 4 * wo2;
    float4 a = *reinterpret_cast<const float4*>(p);
    float4 b = *reinterpret_cast<const float4*>(p + W);
    float2 o;
    o.x = fmaxf(fmaxf(a.x, a.y), fmaxf(b.x, b.y));
    o.y = fmaxf(fmaxf(a.z, a.w), fmaxf(b.z, b.w));
    reinterpret_cast<float2*>(out)[idx] = o;
}

// ---------------------------------------------------------------------------
extern "C" void kernel_launch(void* const* d_in, const int* in_sizes, int n_in,
                              void* d_out, int out_size)
{
    const float* x  = (const float*)d_in[0];
    const float* w1 = (const float*)d_in[1];
    const float* w2 = (const float*)d_in[2];
    const float* w3 = (const float*)d_in[3];
    const float* w4 = (const float*)d_in[4];
    const float* w5 = (const float*)d_in[5];
    const float* w6 = (const float*)d_in[6];
    float* out = (float*)d_out;

    float *A, *B;
    cudaGetSymbolAddress((void**)&A, g_bufA);
    cudaGetSymbolAddress((void**)&B, g_bufB);

    // conv1: x [2,1,1024,256] -> A [2,32,1024,256]
    conv5x5_c1<<<dim3(4, 256, 2), 256>>>(x, w1, A);

    // conv2: A -> B (sliceH=512)
    conv3x3_f2<32, 0><<<dim3(4, 256, 2), 256>>>(A, w2, B, 1024, 256, 512, 1);

    // pool1: B -> A [2,32,512,128]
    {
        int total = 64 * 512 * (128 / 2);
        maxpool2_k<<<(total + 255) / 256, 256>>>(B, A, 64, 1024, 256);
    }

    // conv3: A -> B [2,64,512,128] (sliceH=32)
    conv3x3_f2<32, 0><<<dim3(2, 128, 4), 256>>>(A, w3, B, 512, 128, 32, 2);

    // conv4: B -> A
    conv3x3_f2<64, 0><<<dim3(2, 128, 4), 256>>>(B, w4, A, 512, 128, 32, 2);

    // pool2: A -> B [2,64,256,64]
    {
        int total = 128 * 256 * (64 / 2);
        maxpool2_k<<<(total + 255) / 256, 256>>>(A, B, 128, 512, 128);
    }

    // conv5: B -> A [2,128,256,64] (1x3 middle row)
    conv3x3_f2<64, 1><<<dim3(1, 64, 8), 256>>>(B, w5, A, 256, 64, 1, 4);

    // conv6: A -> out
    conv3x3_f2<128, 1><<<dim3(1, 64, 8), 256>>>(A, w6, out, 256, 64, 1, 4);
}

// round 5
// speedup vs baseline: 2.9461x; 2.0153x over previous
#include <cuda_runtime.h>

// ---------------------------------------------------------------------------
// FrameLevelPartFeatureExtractor — TF32 tensor-core (mma.sync m16n8k8) conv
// pipeline. conv1 scalar fp32; conv2..conv6 implicit GEMM on HMMA.
// All intermediate tensors stored tf32-rounded (RNA); weights pre-rounded and
// pre-packed into B-fragment lane order by a prep kernel. Final layer output
// is plain fp32.
// ---------------------------------------------------------------------------

typedef unsigned int uint;

__device__ __align__(16) float g_bufA[16777216];
__device__ __align__(16) float g_bufB[16777216];
__device__ __align__(16) float g_bufW[138240];   // packed tf32 weights, w2..w6

__device__ __forceinline__ float dlrelu(float v) {
    return v > 0.0f ? v : 0.01f * (0.01f * v);
}
__device__ __forceinline__ float tf32r(float v) {
    uint u; asm("cvt.rna.tf32.f32 %0, %1;" : "=r"(u) : "f"(v));
    return __uint_as_float(u);
}
__device__ __forceinline__ void cp16(unsigned dst, const void* src, int sz) {
    asm volatile("cp.async.cg.shared.global [%0], [%1], 16, %2;\n"
                 :: "r"(dst), "l"(src), "r"(sz));
}
__device__ __forceinline__ void cp4(unsigned dst, const void* src, int sz) {
    asm volatile("cp.async.ca.shared.global [%0], [%1], 4, %2;\n"
                 :: "r"(dst), "l"(src), "r"(sz));
}
__device__ __forceinline__ void cp_commit() {
    asm volatile("cp.async.commit_group;\n" ::);
}
__device__ __forceinline__ void mma_tf32(float* c, uint a0, uint a1, uint a2,
                                         uint a3, uint b0, uint b1) {
    asm volatile(
        "mma.sync.aligned.m16n8k8.row.col.f32.tf32.tf32.f32 "
        "{%0,%1,%2,%3}, {%4,%5,%6,%7}, {%8,%9}, {%0,%1,%2,%3};"
        : "+f"(c[0]), "+f"(c[1]), "+f"(c[2]), "+f"(c[3])
        : "r"(a0), "r"(a1), "r"(a2), "r"(a3), "r"(b0), "r"(b1));
}

// ---------------------------------------------------------------------------
// Weight pack: pk[((ocg*NCH + t)*TAPS + tap)*4 + gg][lane][j] =
//   tf32( W[ocg*32 + gg*8 + lane/4][t*8 + lane%4 + 4j][tapIdx] )
// TAPS==3 -> middle kernel row (taps 3..5).
// ---------------------------------------------------------------------------
__global__ void pack_w(const float* __restrict__ w, float* __restrict__ pk,
                       int CIN, int NCH, int TAPS_, int total)
{
    int idx = blockIdx.x * blockDim.x + threadIdx.x;
    if (idx >= total) return;
    int j    = idx & 1;
    int r1   = idx >> 1;
    int lane = r1 & 31;
    int r2   = r1 >> 5;
    int gg   = r2 & 3;
    int r3   = r2 >> 2;
    int tap  = r3 % TAPS_;
    int r4   = r3 / TAPS_;
    int t    = r4 % NCH;
    int ocg  = r4 / NCH;
    int oc   = ocg * 32 + gg * 8 + (lane >> 2);
    int cin  = t * 8 + (lane & 3) + 4 * j;
    int tapIdx = (TAPS_ == 3) ? (tap + 3) : tap;
    pk[idx] = tf32r(w[(oc * CIN + cin) * 9 + tapIdx]);
}

// ---------------------------------------------------------------------------
// conv1: 5x5, Cin=1, Cout=32 (scalar; epilogue rounds to tf32).
// ---------------------------------------------------------------------------
__global__ __launch_bounds__(256, 2)
void conv5x5_c1(const float* __restrict__ in, const float* __restrict__ wgt,
                float* __restrict__ out)
{
    const int H = 1024, W = 256, SL = 512, TH = 4, TW = 64;
    const int n  = blockIdx.z;
    const int h0 = blockIdx.y * TH;
    const int w0 = blockIdx.x * TW;
    const int tid = threadIdx.x;
    const int ocb = (tid & 3) * 8;
    const int lw  = ((tid >> 2) & 15) * 4;
    const int hh  = tid >> 6;

    __shared__ float si[TH + 4][TW + 4];
    __shared__ float sw[32 * 25];

    for (int i = tid; i < 32 * 25; i += 256) sw[i] = wgt[i];

    const int ss = (h0 / SL) * SL, se = ss + SL;
    for (int i = tid; i < (TH + 4) * (TW + 4); i += 256) {
        int r = i / (TW + 4), c = i % (TW + 4);
        int g = h0 - 2 + r, gc = w0 - 2 + c;
        float v = 0.0f;
        if (g >= ss && g < se && gc >= 0 && gc < W)
            v = in[(n * H + g) * W + gc];
        si[r][c] = v;
    }
    __syncthreads();

    float iv[5][8];
#pragma unroll
    for (int r = 0; r < 5; r++)
#pragma unroll
        for (int c = 0; c < 8; c++)
            iv[r][c] = si[hh + r][lw + c];

    float acc[8][4];
#pragma unroll
    for (int o = 0; o < 8; o++)
#pragma unroll
        for (int x = 0; x < 4; x++) acc[o][x] = 0.0f;

#pragma unroll
    for (int o = 0; o < 8; o++) {
        const float* wp = &sw[(ocb + o) * 25];
#pragma unroll
        for (int r = 0; r < 5; r++)
#pragma unroll
            for (int kc = 0; kc < 5; kc++) {
                float wv = wp[r * 5 + kc];
#pragma unroll
                for (int x = 0; x < 4; x++)
                    acc[o][x] += iv[r][kc + x] * wv;
            }
    }

#pragma unroll
    for (int o = 0; o < 8; o++) {
        float4 v;
        v.x = tf32r(dlrelu(acc[o][0])); v.y = tf32r(dlrelu(acc[o][1]));
        v.z = tf32r(dlrelu(acc[o][2])); v.w = tf32r(dlrelu(acc[o][3]));
        int oc = ocb + o;
        *reinterpret_cast<float4*>(
            &out[(((n * 32) + oc) * H + h0 + hh) * W + w0 + lw]) = v;
    }
}

// ---------------------------------------------------------------------------
// TF32 implicit-GEMM 3x3 focal conv.
// Block tile: 4h x 32w x 32oc. 8 warps = 4 (h row) x 2 (16-oc half).
// Warp: 32w x 16oc via 2 Msub x 2 Nsub m16n8k8 mma, K = cin (8/chunk) x taps.
// ONEROW: sliceH==1 -> 1x3 conv with middle weight row, no h-halo.
// ---------------------------------------------------------------------------
template <int CIN, int ONEROW>
__global__ __launch_bounds__(256, 2)
void conv3x3_mma(const float* __restrict__ in, const float* __restrict__ pk,
                 float* __restrict__ out, int H, int W, int sliceH, int OCG,
                 int doRound)
{
    constexpr int CC    = 8;
    constexpr int ROWS  = ONEROW ? 4 : 6;
    constexpr int TAPS  = ONEROW ? 3 : 9;
    constexpr int PLANE = ONEROW ? 168 : 264;   // words; ==8 mod 32; mult of 4
    constexpr int SI_W  = CC * PLANE;
    constexpr int CHUNK_W = TAPS * 256;         // packed weight words / chunk
    constexpr int NCH   = CIN / CC;
    constexpr int NROWOPS = CC * ROWS * 10;     // 9 cp16 + 1 cp4 per row
    constexpr int NI    = (NROWOPS + 255) / 256;
    constexpr int NWOPS = TAPS * 64;            // 16B ops per chunk
    constexpr int NW    = (NWOPS + 255) / 256;

    __shared__ __align__(16) float si[2][SI_W];
    __shared__ __align__(16) float sb[2][CHUNK_W];

    const int z    = blockIdx.z;
    const int ocg  = z % OCG;
    const int n    = z / OCG;
    const int Cout = OCG * 32;
    const int h0   = blockIdx.y * 4;
    const int w0   = blockIdx.x * 32;
    const int tid  = threadIdx.x;
    const int lane = tid & 31;
    const int wid  = tid >> 5;
    const int warpM = wid & 3;      // h row
    const int warpN = wid >> 2;     // oc half (16 each)
    const int g2 = lane >> 2;       // 0..7
    const int g4 = lane & 3;        // 0..3

    const int ss = ONEROW ? 0 : (h0 / sliceH) * sliceH;
    const int se = ss + sliceH;

    const float* base = in + (size_t)n * CIN * H * W;
    const float* pk0  = pk + (size_t)(ocg * NCH) * CHUNK_W;

    // ---- hoisted input staging descriptors ----
    int di_dst[NI], di_off[NI];
#pragma unroll
    for (int k = 0; k < NI; k++) {
        int i = tid + k * 256;
        int dst = -1, off = -1;
        if (i < NROWOPS) {
            int rowid = i / 10, sub = i - rowid * 10;
            int c = rowid / ROWS, r = rowid - c * ROWS;
            int g = ONEROW ? (h0 + r) : (h0 - 1 + r);
            bool rowok = ONEROW ? true : (g >= ss && g < se);
            int word = c * PLANE + r * 40 + sub * 4;
            if (sub < 9) {
                int gc = w0 - 4 + sub * 4;
                dst = (word * 4) | 1;                    // bit0: 16B op
                off = (rowok && gc >= 0) ? ((c * H + g) * W + gc) : -1;
            } else {
                int gc = w0 + 32;
                dst = word * 4;
                off = (rowok && gc < W) ? ((c * H + g) * W + gc) : -1;
            }
        }
        di_dst[k] = dst; di_off[k] = off;
    }

    unsigned si_s[2], sb_s[2];
    si_s[0] = (unsigned)__cvta_generic_to_shared(&si[0][0]);
    si_s[1] = (unsigned)__cvta_generic_to_shared(&si[1][0]);
    sb_s[0] = (unsigned)__cvta_generic_to_shared(&sb[0][0]);
    sb_s[1] = (unsigned)__cvta_generic_to_shared(&sb[1][0]);

    auto stage = [&](int t, int buf) {
        const float* cb = base + (size_t)t * CC * H * W;
        unsigned sd = si_s[buf];
#pragma unroll
        for (int k = 0; k < NI; k++) {
            int d = di_dst[k];
            if (d >= 0) {
                int off = di_off[k];
                if (d & 1)
                    cp16(sd + (unsigned)(d ^ 1),
                         off >= 0 ? (const void*)(cb + off) : (const void*)cb,
                         off >= 0 ? 16 : 0);
                else
                    cp4(sd + (unsigned)d,
                        off >= 0 ? (const void*)(cb + off) : (const void*)cb,
                        off >= 0 ? 4 : 0);
            }
        }
        const float* wb = pk0 + (size_t)t * CHUNK_W;
        unsigned wd = sb_s[buf];
#pragma unroll
        for (int k = 0; k < NW; k++) {
            int i = tid + k * 256;
            if (NWOPS % 256 == 0 || i < NWOPS)
                cp16(wd + (unsigned)i * 16, wb + i * 4, 16);
        }
        cp_commit();
    };

    float acc[2][2][4];
#pragma unroll
    for (int m = 0; m < 2; m++)
#pragma unroll
        for (int nn = 0; nn < 2; nn++)
#pragma unroll
            for (int x = 0; x < 4; x++) acc[m][nn][x] = 0.0f;

    const int abase = g4 * PLANE + warpM * 40 + g2 + 3;
    const int a2off = 4 * PLANE;

    stage(0, 0);

    for (int t = 0; t < NCH; t++) {
        int buf = t & 1;
        if (t + 1 < NCH) {
            stage(t + 1, buf ^ 1);
            asm volatile("cp.async.wait_group 1;\n" ::);
        } else {
            asm volatile("cp.async.wait_group 0;\n" ::);
        }
        __syncthreads();

        const float* sif = si[buf];
        const float* sbf = sb[buf];
#pragma unroll
        for (int r = 0; r < (ONEROW ? 1 : 3); r++) {
#pragma unroll
            for (int q = 0; q < 3; q++) {
                const int tap = r * 3 + q;
                uint b[2][2];
#pragma unroll
                for (int nn = 0; nn < 2; nn++) {
                    int gg = warpN * 2 + nn;
                    float2 v = *reinterpret_cast<const float2*>(
                        sbf + ((tap * 4 + gg) * 32 + lane) * 2);
                    b[nn][0] = __float_as_uint(v.x);
                    b[nn][1] = __float_as_uint(v.y);
                }
#pragma unroll
                for (int m = 0; m < 2; m++) {
                    int ai = abase + r * 40 + q + m * 16;
                    uint a0 = __float_as_uint(sif[ai]);
                    uint a1 = __float_as_uint(sif[ai + 8]);
                    uint a2 = __float_as_uint(sif[ai + a2off]);
                    uint a3 = __float_as_uint(sif[ai + a2off + 8]);
#pragma unroll
                    for (int nn = 0; nn < 2; nn++)
                        mma_tf32(acc[m][nn], a0, a1, a2, a3,
                                 b[nn][0], b[nn][1]);
                }
            }
        }
        __syncthreads();
    }

    // ---- epilogue ----
    const int h = h0 + warpM;
#pragma unroll
    for (int m = 0; m < 2; m++) {
#pragma unroll
        for (int nn = 0; nn < 2; nn++) {
            int oc = ocg * 32 + warpN * 16 + nn * 8 + 2 * g4;
            int wv = w0 + m * 16 + g2;
            float* p0 = out + ((size_t)(n * Cout + oc) * H + h) * W + wv;
            float* p1 = p0 + (size_t)H * W;
            float v0 = dlrelu(acc[m][nn][0]);
            float v1 = dlrelu(acc[m][nn][1]);
            float v2 = dlrelu(acc[m][nn][2]);
            float v3 = dlrelu(acc[m][nn][3]);
            if (doRound) { v0 = tf32r(v0); v1 = tf32r(v1);
                           v2 = tf32r(v2); v3 = tf32r(v3); }
            p0[0] = v0; p1[0] = v1; p0[8] = v2; p1[8] = v3;
        }
    }
}

// ---------------------------------------------------------------------------
// 2x2 max pool, stride 2 (tf32-rounded values pass through unchanged).
// ---------------------------------------------------------------------------
__global__ void maxpool2_k(const float* __restrict__ in, float* __restrict__ out,
                           int NC, int H, int W)
{
    int HO = H >> 1, WO = W >> 1, WO2 = WO >> 1;
    int total = NC * HO * WO2;
    int idx = blockIdx.x * blockDim.x + threadIdx.x;
    if (idx >= total) return;
    int wo2 = idx % WO2;
    int t   = idx / WO2;
    int ho  = t % HO;
    int ch  = t / HO;
    const float* p = in + ((long)ch * H + 2 * ho) * W + 4 * wo2;
    float4 a = *reinterpret_cast<const float4*>(p);
    float4 b = *reinterpret_cast<const float4*>(p + W);
    float2 o;
    o.x = fmaxf(fmaxf(a.x, a.y), fmaxf(b.x, b.y));
    o.y = fmaxf(fmaxf(a.z, a.w), fmaxf(b.z, b.w));
    reinterpret_cast<float2*>(out)[idx] = o;
}

// ---------------------------------------------------------------------------
extern "C" void kernel_launch(void* const* d_in, const int* in_sizes, int n_in,
                              void* d_out, int out_size)
{
    const float* x  = (const float*)d_in[0];
    const float* w1 = (const float*)d_in[1];
    const float* w2 = (const float*)d_in[2];
    const float* w3 = (const float*)d_in[3];
    const float* w4 = (const float*)d_in[4];
    const float* w5 = (const float*)d_in[5];
    const float* w6 = (const float*)d_in[6];
    float* out = (float*)d_out;

    float *A, *B, *Wp;
    cudaGetSymbolAddress((void**)&A, g_bufA);
    cudaGetSymbolAddress((void**)&B, g_bufB);
    cudaGetSymbolAddress((void**)&Wp, g_bufW);

    // Packed weight regions (word offsets)
    const int o2 = 0, o3 = 9216, o4 = 27648, o5 = 64512, o6 = 89088;

    // Prep: round + pack weights into B-fragment order.
    pack_w<<<9216 / 256, 256>>>(w2, Wp + o2, 32, 4, 9, 9216);
    pack_w<<<18432 / 256, 256>>>(w3, Wp + o3, 32, 4, 9, 18432);
    pack_w<<<36864 / 256, 256>>>(w4, Wp + o4, 64, 8, 9, 36864);
    pack_w<<<24576 / 256, 256>>>(w5, Wp + o5, 64, 8, 3, 24576);
    pack_w<<<49152 / 256, 256>>>(w6, Wp + o6, 128, 16, 3, 49152);

    // conv1: x [2,1,1024,256] -> A [2,32,1024,256] (tf32-rounded out)
    conv5x5_c1<<<dim3(4, 256, 2), 256>>>(x, w1, A);

    // conv2: A -> B (sliceH=512)
    conv3x3_mma<32, 0><<<dim3(8, 256, 2), 256>>>(A, Wp + o2, B,
                                                 1024, 256, 512, 1, 1);

    // pool1: B -> A [2,32,512,128]
    {
        int total = 64 * 512 * (128 / 2);
        maxpool2_k<<<(total + 255) / 256, 256>>>(B, A, 64, 1024, 256);
    }

    // conv3: A -> B [2,64,512,128] (sliceH=32)
    conv3x3_mma<32, 0><<<dim3(4, 128, 4), 256>>>(A, Wp + o3, B,
                                                 512, 128, 32, 2, 1);

    // conv4: B -> A
    conv3x3_mma<64, 0><<<dim3(4, 128, 4), 256>>>(B, Wp + o4, A,
                                                 512, 128, 32, 2, 1);

    // pool2: A -> B [2,64,256,64]
    {
        int total = 128 * 256 * (64 / 2);
        maxpool2_k<<<(total + 255) / 256, 256>>>(A, B, 128, 512, 128);
    }

    // conv5: B -> A [2,128,256,64] (1x3 middle row)
    conv3x3_mma<64, 1><<<dim3(2, 64, 8), 256>>>(B, Wp + o5, A,
                                                256, 64, 1, 4, 1);

    // conv6: A -> out (final: no rounding)
    conv3x3_mma<128, 1><<<dim3(2, 64, 8), 256>>>(A, Wp + o6, out,
                                                 256, 64, 1, 4, 0);
}

// round 7
// speedup vs baseline: 3.0752x; 1.0438x over previous
#include <cuda_runtime.h>

// ---------------------------------------------------------------------------
// FrameLevelPartFeatureExtractor — TF32 tensor-core (mma.sync m16n8k8) conv
// pipeline. conv1 packed-f32x2 scalar; conv2..conv6 implicit GEMM on HMMA.
// conv2/conv4 fuse the 2x2 maxpool into their epilogue (pool stash ALIASES
// the dead si double-buffer -> fits 48KB static smem). Single fused weight
// pack kernel. All intermediates tf32-rounded; final layer plain fp32.
// ---------------------------------------------------------------------------

typedef unsigned int uint;
typedef unsigned long long u64;

__device__ __align__(16) float g_bufA[16777216];
__device__ __align__(16) float g_bufB[16777216];
__device__ __align__(16) float g_bufW[138240];   // packed tf32 weights, w2..w6

__device__ __forceinline__ float dlrelu(float v) {
    return v > 0.0f ? v : 0.01f * (0.01f * v);
}
__device__ __forceinline__ float tf32r(float v) {
    uint u; asm("cvt.rna.tf32.f32 %0, %1;" : "=r"(u) : "f"(v));
    return __uint_as_float(u);
}
__device__ __forceinline__ void cp16(unsigned dst, const void* src, int sz) {
    asm volatile("cp.async.cg.shared.global [%0], [%1], 16, %2;\n"
                 :: "r"(dst), "l"(src), "r"(sz));
}
__device__ __forceinline__ void cp4(unsigned dst, const void* src, int sz) {
    asm volatile("cp.async.ca.shared.global [%0], [%1], 4, %2;\n"
                 :: "r"(dst), "l"(src), "r"(sz));
}
__device__ __forceinline__ void cp_commit() {
    asm volatile("cp.async.commit_group;\n" ::);
}
__device__ __forceinline__ void mma_tf32(float* c, uint a0, uint a1, uint a2,
                                         uint a3, uint b0, uint b1) {
    asm volatile(
        "mma.sync.aligned.m16n8k8.row.col.f32.tf32.tf32.f32 "
        "{%0,%1,%2,%3}, {%4,%5,%6,%7}, {%8,%9}, {%0,%1,%2,%3};"
        : "+f"(c[0]), "+f"(c[1]), "+f"(c[2]), "+f"(c[3])
        : "r"(a0), "r"(a1), "r"(a2), "r"(a3), "r"(b0), "r"(b1));
}
__device__ __forceinline__ u64 dup_f(float v) {
    u64 r; asm("mov.b64 %0, {%1, %1};" : "=l"(r) : "f"(v)); return r;
}
__device__ __forceinline__ void ffma2(u64& d, u64 a, u64 b) {
    asm("fma.rn.f32x2 %0, %1, %2, %0;" : "+l"(d) : "l"(a), "l"(b));
}
__device__ __forceinline__ float2 unpk(u64 a) {
    float2 f; asm("mov.b64 {%0, %1}, %2;" : "=f"(f.x), "=f"(f.y) : "l"(a));
    return f;
}

// ---------------------------------------------------------------------------
// Fused weight pack for layers 2..6.
// Element layout per layer: pk[((ocg*NCH + t)*TAPS + tap)*4 + gg][lane][j] =
//   tf32( W[ocg*32 + gg*8 + lane/4][t*8 + lane%4 + 4j][tapIdx] )
// TAPS==3 -> middle kernel row (taps 3..5).
// ---------------------------------------------------------------------------
__global__ void pack_all(const float* __restrict__ w2, const float* __restrict__ w3,
                         const float* __restrict__ w4, const float* __restrict__ w5,
                         const float* __restrict__ w6, float* __restrict__ pk)
{
    int idx = blockIdx.x * blockDim.x + threadIdx.x;
    if (idx >= 138240) return;
    const float* w; int CIN, NCH, TAPS_, local;
    if (idx < 9216)       { w = w2; CIN = 32;  NCH = 4;  TAPS_ = 9; local = idx; }
    else if (idx < 27648) { w = w3; CIN = 32;  NCH = 4;  TAPS_ = 9; local = idx - 9216; }
    else if (idx < 64512) { w = w4; CIN = 64;  NCH = 8;  TAPS_ = 9; local = idx - 27648; }
    else if (idx < 89088) { w = w5; CIN = 64;  NCH = 8;  TAPS_ = 3; local = idx - 64512; }
    else                  { w = w6; CIN = 128; NCH = 16; TAPS_ = 3; local = idx - 89088; }
    int j    = local & 1;
    int r1   = local >> 1;
    int lane = r1 & 31;
    int r2   = r1 >> 5;
    int gg   = r2 & 3;
    int r3   = r2 >> 2;
    int tap  = r3 % TAPS_;
    int r4   = r3 / TAPS_;
    int t    = r4 % NCH;
    int ocg  = r4 / NCH;
    int oc   = ocg * 32 + gg * 8 + (lane >> 2);
    int cin  = t * 8 + (lane & 3) + 4 * j;
    int tapIdx = (TAPS_ == 3) ? (tap + 3) : tap;
    pk[idx] = tf32r(w[(oc * CIN + cin) * 9 + tapIdx]);
}

// ---------------------------------------------------------------------------
// conv1: 5x5, Cin=1, Cout=32, packed f32x2 FMA (oc-paired accumulators).
// Block 256 thr -> 32 oc x 4 h x 64 w; thread 4 oc-pairs x 4 w.
// ---------------------------------------------------------------------------
__global__ __launch_bounds__(256, 2)
void conv5x5_c1(const float* __restrict__ in, const float* __restrict__ wgt,
                float* __restrict__ out)
{
    const int H = 1024, W = 256, SL = 512, TH = 4, TW = 64;
    const int n  = blockIdx.z;
    const int h0 = blockIdx.y * TH;
    const int w0 = blockIdx.x * TW;
    const int tid = threadIdx.x;
    const int ocb = (tid & 3) * 8;          // 8 oc -> 4 pairs
    const int op0 = (tid & 3) * 4;          // first pair index (of 16)
    const int lw  = ((tid >> 2) & 15) * 4;
    const int hh  = tid >> 6;

    __shared__ float si[TH + 4][TW + 4];
    __shared__ float2 swp[16][25];          // oc-paired weights

    for (int i = tid; i < 32 * 25; i += 256) {
        int o = i / 25, t = i % 25;
        float v = wgt[i];
        if (o & 1) swp[o >> 1][t].y = v; else swp[o >> 1][t].x = v;
    }

    const int ss = (h0 / SL) * SL, se = ss + SL;
    for (int i = tid; i < (TH + 4) * (TW + 4); i += 256) {
        int r = i / (TW + 4), c = i % (TW + 4);
        int g = h0 - 2 + r, gc = w0 - 2 + c;
        float v = 0.0f;
        if (g >= ss && g < se && gc >= 0 && gc < W)
            v = in[(n * H + g) * W + gc];
        si[r][c] = v;
    }
    __syncthreads();

    u64 dup[5][8];
#pragma unroll
    for (int r = 0; r < 5; r++)
#pragma unroll
        for (int c = 0; c < 8; c++)
            dup[r][c] = dup_f(si[hh + r][lw + c]);

    u64 acc[4][4];
#pragma unroll
    for (int p = 0; p < 4; p++)
#pragma unroll
        for (int x = 0; x < 4; x++) acc[p][x] = 0ULL;

#pragma unroll
    for (int p = 0; p < 4; p++) {
        const u64* wp = reinterpret_cast<const u64*>(&swp[op0 + p][0]);
#pragma unroll
        for (int r = 0; r < 5; r++)
#pragma unroll
            for (int kc = 0; kc < 5; kc++) {
                u64 wv = wp[r * 5 + kc];
#pragma unroll
                for (int x = 0; x < 4; x++)
                    ffma2(acc[p][x], dup[r][kc + x], wv);
            }
    }

#pragma unroll
    for (int p = 0; p < 4; p++) {
        float lo[4], hi[4];
#pragma unroll
        for (int x = 0; x < 4; x++) {
            float2 f = unpk(acc[p][x]);
            lo[x] = tf32r(dlrelu(f.x));
            hi[x] = tf32r(dlrelu(f.y));
        }
        int oc0 = ocb + 2 * p;
        float* o0 = &out[(((n * 32) + oc0) * H + h0 + hh) * W + w0 + lw];
        float* o1 = o0 + (size_t)H * W;
        *reinterpret_cast<float4*>(o0) = make_float4(lo[0], lo[1], lo[2], lo[3]);
        *reinterpret_cast<float4*>(o1) = make_float4(hi[0], hi[1], hi[2], hi[3]);
    }
}

// ---------------------------------------------------------------------------
// TF32 implicit-GEMM 3x3 focal conv.
// Block tile: 4h x 32w x 32oc. 8 warps = 4 (h row) x 2 (16-oc half).
// Warp: 32w x 16oc via 2 Msub x 2 Nsub m16n8k8 mma, K = cin (8/chunk) x taps.
// ONEROW: sliceH==1 -> 1x3 conv with middle weight row, no h-halo.
// POOL: fuse 2x2 maxpool in epilogue; pool stash ALIASES si (dead there).
// ---------------------------------------------------------------------------
template <int CIN, int ONEROW, int POOL>
__global__ __launch_bounds__(256, 2)
void conv3x3_mma(const float* __restrict__ in, const float* __restrict__ pk,
                 float* __restrict__ out, int H, int W, int sliceH, int OCG,
                 int doRound)
{
    constexpr int CC    = 8;
    constexpr int ROWS  = ONEROW ? 4 : 6;
    constexpr int TAPS  = ONEROW ? 3 : 9;
    constexpr int PLANE = ONEROW ? 168 : 264;   // words; ==8 mod 32; mult of 4
    constexpr int SI_W  = CC * PLANE;
    constexpr int CHUNK_W = TAPS * 256;
    constexpr int NCH   = CIN / CC;
    constexpr int NROWOPS = CC * ROWS * 10;     // 9 cp16 + 1 cp4 per row
    constexpr int NI    = (NROWOPS + 255) / 256;
    constexpr int NWOPS = TAPS * 64;
    constexpr int NW    = (NWOPS + 255) / 256;

    // POOL stash needs 4*32*33 = 4224 words = 16896B; si (non-ONEROW) is
    // 2*8*264 = 4224 words. Alias them (si is dead at epilogue time).
    static_assert(!POOL || 2 * SI_W >= 4 * 32 * 33, "pool stash fits in si");

    __shared__ __align__(16) float si[2][SI_W];
    __shared__ __align__(16) float sb[2][CHUNK_W];
    float* sO = &si[0][0];   // alias (POOL epilogue only)

    const int z    = blockIdx.z;
    const int ocg  = z % OCG;
    const int n    = z / OCG;
    const int Cout = OCG * 32;
    const int h0   = blockIdx.y * 4;
    const int w0   = blockIdx.x * 32;
    const int tid  = threadIdx.x;
    const int lane = tid & 31;
    const int wid  = tid >> 5;
    const int warpM = wid & 3;
    const int warpN = wid >> 2;
    const int g2 = lane >> 2;
    const int g4 = lane & 3;

    const int ss = ONEROW ? 0 : (h0 / sliceH) * sliceH;
    const int se = ss + sliceH;

    const float* base = in + (size_t)n * CIN * H * W;
    const float* pk0  = pk + (size_t)(ocg * NCH) * CHUNK_W;

    // ---- hoisted input staging descriptors ----
    int di_dst[NI], di_off[NI];
#pragma unroll
    for (int k = 0; k < NI; k++) {
        int i = tid + k * 256;
        int dst = -1, off = -1;
        if (i < NROWOPS) {
            int rowid = i / 10, sub = i - rowid * 10;
            int c = rowid / ROWS, r = rowid - c * ROWS;
            int g = ONEROW ? (h0 + r) : (h0 - 1 + r);
            bool rowok = ONEROW ? true : (g >= ss && g < se);
            int word = c * PLANE + r * 40 + sub * 4;
            if (sub < 9) {
                int gc = w0 - 4 + sub * 4;
                dst = (word * 4) | 1;
                off = (rowok && gc >= 0) ? ((c * H + g) * W + gc) : -1;
            } else {
                int gc = w0 + 32;
                dst = word * 4;
                off = (rowok && gc < W) ? ((c * H + g) * W + gc) : -1;
            }
        }
        di_dst[k] = dst; di_off[k] = off;
    }

    unsigned si_s[2], sb_s[2];
    si_s[0] = (unsigned)__cvta_generic_to_shared(&si[0][0]);
    si_s[1] = (unsigned)__cvta_generic_to_shared(&si[1][0]);
    sb_s[0] = (unsigned)__cvta_generic_to_shared(&sb[0][0]);
    sb_s[1] = (unsigned)__cvta_generic_to_shared(&sb[1][0]);

    auto stage = [&](int t, int buf) {
        const float* cb = base + (size_t)t * CC * H * W;
        unsigned sd = si_s[buf];
#pragma unroll
        for (int k = 0; k < NI; k++) {
            int d = di_dst[k];
            if (d >= 0) {
                int off = di_off[k];
                if (d & 1)
                    cp16(sd + (unsigned)(d ^ 1),
                         off >= 0 ? (const void*)(cb + off) : (const void*)cb,
                         off >= 0 ? 16 : 0);
                else
                    cp4(sd + (unsigned)d,
                        off >= 0 ? (const void*)(cb + off) : (const void*)cb,
                        off >= 0 ? 4 : 0);
            }
        }
        const float* wb = pk0 + (size_t)t * CHUNK_W;
        unsigned wd = sb_s[buf];
#pragma unroll
        for (int k = 0; k < NW; k++) {
            int i = tid + k * 256;
            if (NWOPS % 256 == 0 || i < NWOPS)
                cp16(wd + (unsigned)i * 16, wb + i * 4, 16);
        }
        cp_commit();
    };

    float acc[2][2][4];
#pragma unroll
    for (int m = 0; m < 2; m++)
#pragma unroll
        for (int nn = 0; nn < 2; nn++)
#pragma unroll
            for (int x = 0; x < 4; x++) acc[m][nn][x] = 0.0f;

    const int abase = g4 * PLANE + warpM * 40 + g2 + 3;
    const int a2off = 4 * PLANE;

    stage(0, 0);

    for (int t = 0; t < NCH; t++) {
        int buf = t & 1;
        if (t + 1 < NCH) {
            stage(t + 1, buf ^ 1);
            asm volatile("cp.async.wait_group 1;\n" ::);
        } else {
            asm volatile("cp.async.wait_group 0;\n" ::);
        }
        __syncthreads();

        const float* sif = si[buf];
        const float* sbf = sb[buf];
#pragma unroll
        for (int r = 0; r < (ONEROW ? 1 : 3); r++) {
#pragma unroll
            for (int q = 0; q < 3; q++) {
                const int tap = r * 3 + q;
                uint b[2][2];
#pragma unroll
                for (int nn = 0; nn < 2; nn++) {
                    int gg = warpN * 2 + nn;
                    float2 v = *reinterpret_cast<const float2*>(
                        sbf + ((tap * 4 + gg) * 32 + lane) * 2);
                    b[nn][0] = __float_as_uint(v.x);
                    b[nn][1] = __float_as_uint(v.y);
                }
#pragma unroll
                for (int m = 0; m < 2; m++) {
                    int ai = abase + r * 40 + q + m * 16;
                    uint a0 = __float_as_uint(sif[ai]);
                    uint a1 = __float_as_uint(sif[ai + 8]);
                    uint a2 = __float_as_uint(sif[ai + a2off]);
                    uint a3 = __float_as_uint(sif[ai + a2off + 8]);
#pragma unroll
                    for (int nn = 0; nn < 2; nn++)
                        mma_tf32(acc[m][nn], a0, a1, a2, a3,
                                 b[nn][0], b[nn][1]);
                }
            }
        }
        __syncthreads();
    }

    // ---- epilogue ----
    if (POOL) {
        // si is dead now (trailing __syncthreads above). Stash activated
        // + rounded values into the aliased sO, then pooled write.
#pragma unroll
        for (int m = 0; m < 2; m++)
#pragma unroll
            for (int nn = 0; nn < 2; nn++) {
                int ocl = warpN * 16 + nn * 8 + 2 * g4;
#pragma unroll
                for (int x = 0; x < 4; x++) {
                    int wl = m * 16 + g2 + ((x >> 1) ? 8 : 0);
                    sO[warpM * (32 * 33) + wl * 33 + ocl + (x & 1)] =
                        tf32r(dlrelu(acc[m][nn][x]));
                }
            }
        __syncthreads();
        const int H2 = H >> 1, W2 = W >> 1;
        const int pw = tid & 15, ph = (tid >> 4) & 1, ob = tid >> 5;
#pragma unroll
        for (int k = 0; k < 4; k++) {
            int ocl = ob + k * 8;
            const float* s0 = sO + (2 * ph) * (32 * 33) + (2 * pw) * 33 + ocl;
            float v = fmaxf(fmaxf(s0[0], s0[33]),
                            fmaxf(s0[32 * 33], s0[32 * 33 + 33]));
            out[((size_t)(n * Cout + ocg * 32 + ocl) * H2 + (h0 >> 1) + ph) * W2
                + (w0 >> 1) + pw] = v;
        }
    } else {
        const int h = h0 + warpM;
#pragma unroll
        for (int m = 0; m < 2; m++) {
#pragma unroll
            for (int nn = 0; nn < 2; nn++) {
                int oc = ocg * 32 + warpN * 16 + nn * 8 + 2 * g4;
                int wv = w0 + m * 16 + g2;
                float* p0 = out + ((size_t)(n * Cout + oc) * H + h) * W + wv;
                float* p1 = p0 + (size_t)H * W;
                float v0 = dlrelu(acc[m][nn][0]);
                float v1 = dlrelu(acc[m][nn][1]);
                float v2 = dlrelu(acc[m][nn][2]);
                float v3 = dlrelu(acc[m][nn][3]);
                if (doRound) { v0 = tf32r(v0); v1 = tf32r(v1);
                               v2 = tf32r(v2); v3 = tf32r(v3); }
                p0[0] = v0; p1[0] = v1; p0[8] = v2; p1[8] = v3;
            }
        }
    }
}

// ---------------------------------------------------------------------------
extern "C" void kernel_launch(void* const* d_in, const int* in_sizes, int n_in,
                              void* d_out, int out_size)
{
    const float* x  = (const float*)d_in[0];
    const float* w1 = (const float*)d_in[1];
    const float* w2 = (const float*)d_in[2];
    const float* w3 = (const float*)d_in[3];
    const float* w4 = (const float*)d_in[4];
    const float* w5 = (const float*)d_in[5];
    const float* w6 = (const float*)d_in[6];
    float* out = (float*)d_out;

    float *A, *B, *Wp;
    cudaGetSymbolAddress((void**)&A, g_bufA);
    cudaGetSymbolAddress((void**)&B, g_bufB);
    cudaGetSymbolAddress((void**)&Wp, g_bufW);

    const int o2 = 0, o3 = 9216, o4 = 27648, o5 = 64512, o6 = 89088;

    // Prep: fused round + pack of all conv weights.
    pack_all<<<540, 256>>>(w2, w3, w4, w5, w6, Wp);

    // conv1: x [2,1,1024,256] -> A [2,32,1024,256]
    conv5x5_c1<<<dim3(4, 256, 2), 256>>>(x, w1, A);

    // conv2 (+pool1 fused): A -> B [2,32,512,128]
    conv3x3_mma<32, 0, 1><<<dim3(8, 256, 2), 256>>>(A, Wp + o2, B,
                                                    1024, 256, 512, 1, 1);

    // conv3: B -> A [2,64,512,128] (sliceH=32)
    conv3x3_mma<32, 0, 0><<<dim3(4, 128, 4), 256>>>(B, Wp + o3, A,
                                                    512, 128, 32, 2, 1);

    // conv4 (+pool2 fused): A -> B [2,64,256,64]
    conv3x3_mma<64, 0, 1><<<dim3(4, 128, 4), 256>>>(A, Wp + o4, B,
                                                    512, 128, 32, 2, 1);

    // conv5: B -> A [2,128,256,64] (1x3 middle row)
    conv3x3_mma<64, 1, 0><<<dim3(2, 64, 8), 256>>>(B, Wp + o5, A,
                                                   256, 64, 1, 4, 1);

    // conv6: A -> out (final: no rounding)
    conv3x3_mma<128, 1, 0><<<dim3(2, 64, 8), 256>>>(A, Wp + o6, out,
                                                    256, 64, 1, 4, 0);
}

// round 8
// speedup vs baseline: 3.3238x; 1.0808x over previous
#include <cuda_runtime.h>

// ---------------------------------------------------------------------------
// FrameLevelPartFeatureExtractor — TF32 tensor-core (mma.sync m16n8k8) conv
// pipeline. conv1 packed-f32x2; conv2..conv6 implicit GEMM on HMMA with
// 8h x 32w x 32oc block tile (warp = 1 h-row, M=32 x N=32 -> 256B LDS/mma).
// conv2/conv4 fuse the 2x2 maxpool into their epilogue (stash aliases the
// dead si/sb arena). Single fused weight pack kernel. Intermediates
// tf32-rounded; final layer plain fp32.
// ---------------------------------------------------------------------------

typedef unsigned int uint;
typedef unsigned long long u64;

__device__ __align__(16) float g_bufA[16777216];
__device__ __align__(16) float g_bufB[16777216];
__device__ __align__(16) float g_bufW[138240];   // packed tf32 weights, w2..w6

__device__ __forceinline__ float dlrelu(float v) {
    return v > 0.0f ? v : 0.01f * (0.01f * v);
}
__device__ __forceinline__ float tf32r(float v) {
    uint u; asm("cvt.rna.tf32.f32 %0, %1;" : "=r"(u) : "f"(v));
    return __uint_as_float(u);
}
__device__ __forceinline__ void cp16(unsigned dst, const void* src, int sz) {
    asm volatile("cp.async.cg.shared.global [%0], [%1], 16, %2;\n"
                 :: "r"(dst), "l"(src), "r"(sz));
}
__device__ __forceinline__ void cp4(unsigned dst, const void* src, int sz) {
    asm volatile("cp.async.ca.shared.global [%0], [%1], 4, %2;\n"
                 :: "r"(dst), "l"(src), "r"(sz));
}
__device__ __forceinline__ void cp_commit() {
    asm volatile("cp.async.commit_group;\n" ::);
}
__device__ __forceinline__ void mma_tf32(float* c, uint a0, uint a1, uint a2,
                                         uint a3, uint b0, uint b1) {
    asm volatile(
        "mma.sync.aligned.m16n8k8.row.col.f32.tf32.tf32.f32 "
        "{%0,%1,%2,%3}, {%4,%5,%6,%7}, {%8,%9}, {%0,%1,%2,%3};"
        : "+f"(c[0]), "+f"(c[1]), "+f"(c[2]), "+f"(c[3])
        : "r"(a0), "r"(a1), "r"(a2), "r"(a3), "r"(b0), "r"(b1));
}
__device__ __forceinline__ u64 dup_f(float v) {
    u64 r; asm("mov.b64 %0, {%1, %1};" : "=l"(r) : "f"(v)); return r;
}
__device__ __forceinline__ void ffma2(u64& d, u64 a, u64 b) {
    asm("fma.rn.f32x2 %0, %1, %2, %0;" : "+l"(d) : "l"(a), "l"(b));
}
__device__ __forceinline__ float2 unpk(u64 a) {
    float2 f; asm("mov.b64 {%0, %1}, %2;" : "=f"(f.x), "=f"(f.y) : "l"(a));
    return f;
}

// ---------------------------------------------------------------------------
// Fused weight pack for layers 2..6 (layout unchanged from R5/R7):
// pk[((ocg*NCH + t)*TAPS + tap)*4 + gg][lane][j] =
//   tf32( W[ocg*32 + gg*8 + lane/4][t*8 + lane%4 + 4j][tapIdx] )
// ---------------------------------------------------------------------------
__global__ void pack_all(const float* __restrict__ w2, const float* __restrict__ w3,
                         const float* __restrict__ w4, const float* __restrict__ w5,
                         const float* __restrict__ w6, float* __restrict__ pk)
{
    int idx = blockIdx.x * blockDim.x + threadIdx.x;
    if (idx >= 138240) return;
    const float* w; int CIN, NCH, TAPS_, local;
    if (idx < 9216)       { w = w2; CIN = 32;  NCH = 4;  TAPS_ = 9; local = idx; }
    else if (idx < 27648) { w = w3; CIN = 32;  NCH = 4;  TAPS_ = 9; local = idx - 9216; }
    else if (idx < 64512) { w = w4; CIN = 64;  NCH = 8;  TAPS_ = 9; local = idx - 27648; }
    else if (idx < 89088) { w = w5; CIN = 64;  NCH = 8;  TAPS_ = 3; local = idx - 64512; }
    else                  { w = w6; CIN = 128; NCH = 16; TAPS_ = 3; local = idx - 89088; }
    int j    = local & 1;
    int r1   = local >> 1;
    int lane = r1 & 31;
    int r2   = r1 >> 5;
    int gg   = r2 & 3;
    int r3   = r2 >> 2;
    int tap  = r3 % TAPS_;
    int r4   = r3 / TAPS_;
    int t    = r4 % NCH;
    int ocg  = r4 / NCH;
    int oc   = ocg * 32 + gg * 8 + (lane >> 2);
    int cin  = t * 8 + (lane & 3) + 4 * j;
    int tapIdx = (TAPS_ == 3) ? (tap + 3) : tap;
    pk[idx] = tf32r(w[(oc * CIN + cin) * 9 + tapIdx]);
}

// ---------------------------------------------------------------------------
// conv1: 5x5, Cin=1, Cout=32, packed f32x2 FMA.
// ---------------------------------------------------------------------------
__global__ __launch_bounds__(256, 2)
void conv5x5_c1(const float* __restrict__ in, const float* __restrict__ wgt,
                float* __restrict__ out)
{
    const int H = 1024, W = 256, SL = 512, TH = 4, TW = 64;
    const int n  = blockIdx.z;
    const int h0 = blockIdx.y * TH;
    const int w0 = blockIdx.x * TW;
    const int tid = threadIdx.x;
    const int ocb = (tid & 3) * 8;
    const int op0 = (tid & 3) * 4;
    const int lw  = ((tid >> 2) & 15) * 4;
    const int hh  = tid >> 6;

    __shared__ float si[TH + 4][TW + 4];
    __shared__ float2 swp[16][25];

    for (int i = tid; i < 32 * 25; i += 256) {
        int o = i / 25, t = i % 25;
        float v = wgt[i];
        if (o & 1) swp[o >> 1][t].y = v; else swp[o >> 1][t].x = v;
    }

    const int ss = (h0 / SL) * SL, se = ss + SL;
    for (int i = tid; i < (TH + 4) * (TW + 4); i += 256) {
        int r = i / (TW + 4), c = i % (TW + 4);
        int g = h0 - 2 + r, gc = w0 - 2 + c;
        float v = 0.0f;
        if (g >= ss && g < se && gc >= 0 && gc < W)
            v = in[(n * H + g) * W + gc];
        si[r][c] = v;
    }
    __syncthreads();

    u64 dup[5][8];
#pragma unroll
    for (int r = 0; r < 5; r++)
#pragma unroll
        for (int c = 0; c < 8; c++)
            dup[r][c] = dup_f(si[hh + r][lw + c]);

    u64 acc[4][4];
#pragma unroll
    for (int p = 0; p < 4; p++)
#pragma unroll
        for (int x = 0; x < 4; x++) acc[p][x] = 0ULL;

#pragma unroll
    for (int p = 0; p < 4; p++) {
        const u64* wp = reinterpret_cast<const u64*>(&swp[op0 + p][0]);
#pragma unroll
        for (int r = 0; r < 5; r++)
#pragma unroll
            for (int kc = 0; kc < 5; kc++) {
                u64 wv = wp[r * 5 + kc];
#pragma unroll
                for (int x = 0; x < 4; x++)
                    ffma2(acc[p][x], dup[r][kc + x], wv);
            }
    }

#pragma unroll
    for (int p = 0; p < 4; p++) {
        float lo[4], hi[4];
#pragma unroll
        for (int x = 0; x < 4; x++) {
            float2 f = unpk(acc[p][x]);
            lo[x] = tf32r(dlrelu(f.x));
            hi[x] = tf32r(dlrelu(f.y));
        }
        int oc0 = ocb + 2 * p;
        float* o0 = &out[(((n * 32) + oc0) * H + h0 + hh) * W + w0 + lw];
        float* o1 = o0 + (size_t)H * W;
        *reinterpret_cast<float4*>(o0) = make_float4(lo[0], lo[1], lo[2], lo[3]);
        *reinterpret_cast<float4*>(o1) = make_float4(hi[0], hi[1], hi[2], hi[3]);
    }
}

// ---------------------------------------------------------------------------
// TF32 implicit-GEMM 3x3 focal conv.
// Block tile: 8h x 32w x 32oc. 8 warps; warp = one h row, M=32 x N=32
// (2 M-subtiles x 4 N-subtiles = 8 mmas per tap) -> 256B LDS per mma.
// ONEROW: sliceH==1 -> 1x3 conv with middle weight row, no h-halo.
// POOL: fuse 2x2 maxpool in epilogue; stash aliases the dead smem arena.
// ---------------------------------------------------------------------------
template <int CIN, int ONEROW, int POOL>
__global__ __launch_bounds__(256, 2)
void conv3x3_mma(const float* __restrict__ in, const float* __restrict__ pk,
                 float* __restrict__ out, int H, int W, int sliceH, int OCG,
                 int doRound)
{
    constexpr int CC    = 8;
    constexpr int TH    = 8;
    constexpr int ROWS  = ONEROW ? TH : (TH + 2);
    constexpr int TAPS  = ONEROW ? 3 : 9;
    constexpr int PLANE = ONEROW ? 328 : 424;   // >=ROWS*40, ==8 mod 32, /4
    constexpr int SI_W  = CC * PLANE;
    constexpr int CHUNK_W = TAPS * 256;
    constexpr int NCH   = CIN / CC;
    constexpr int NROWOPS = CC * ROWS * 10;     // 9 cp16 + 1 cp4 per row
    constexpr int NI    = (NROWOPS + 255) / 256;
    constexpr int NWOPS = TAPS * 64;
    constexpr int NW    = (NWOPS + 255) / 256;
    constexpr int ARENA = 2 * SI_W + 2 * CHUNK_W;

    // POOL stash: 8 * 32 * 33 = 8448 words, aliases full (dead) arena.
    static_assert(!POOL || ARENA >= TH * 32 * 33, "pool stash fits");

    __shared__ __align__(16) float arena[ARENA];
    float* si[2] = { arena, arena + SI_W };
    float* sb[2] = { arena + 2 * SI_W, arena + 2 * SI_W + CHUNK_W };
    float* sO = arena;

    const int z    = blockIdx.z;
    const int ocg  = z % OCG;
    const int n    = z / OCG;
    const int Cout = OCG * 32;
    const int h0   = blockIdx.y * TH;
    const int w0   = blockIdx.x * 32;
    const int tid  = threadIdx.x;
    const int lane = tid & 31;
    const int wid  = tid >> 5;      // h row within tile
    const int g2 = lane >> 2;
    const int g4 = lane & 3;

    const int ss = ONEROW ? 0 : (h0 / sliceH) * sliceH;
    const int se = ss + sliceH;

    const float* base = in + (size_t)n * CIN * H * W;
    const float* pk0  = pk + (size_t)(ocg * NCH) * CHUNK_W;

    // ---- hoisted input staging descriptors ----
    int di_dst[NI], di_off[NI];
#pragma unroll
    for (int k = 0; k < NI; k++) {
        int i = tid + k * 256;
        int dst = -1, off = -1;
        if (i < NROWOPS) {
            int rowid = i / 10, sub = i - rowid * 10;
            int c = rowid / ROWS, r = rowid - c * ROWS;
            int g = ONEROW ? (h0 + r) : (h0 - 1 + r);
            bool rowok = ONEROW ? true : (g >= ss && g < se);
            int word = c * PLANE + r * 40 + sub * 4;
            if (sub < 9) {
                int gc = w0 - 4 + sub * 4;
                dst = (word * 4) | 1;
                off = (rowok && gc >= 0) ? ((c * H + g) * W + gc) : -1;
            } else {
                int gc = w0 + 32;
                dst = word * 4;
                off = (rowok && gc < W) ? ((c * H + g) * W + gc) : -1;
            }
        }
        di_dst[k] = dst; di_off[k] = off;
    }

    unsigned si_s[2], sb_s[2];
    si_s[0] = (unsigned)__cvta_generic_to_shared(si[0]);
    si_s[1] = (unsigned)__cvta_generic_to_shared(si[1]);
    sb_s[0] = (unsigned)__cvta_generic_to_shared(sb[0]);
    sb_s[1] = (unsigned)__cvta_generic_to_shared(sb[1]);

    auto stage = [&](int t, int buf) {
        const float* cb = base + (size_t)t * CC * H * W;
        unsigned sd = si_s[buf];
#pragma unroll
        for (int k = 0; k < NI; k++) {
            int d = di_dst[k];
            if (d >= 0) {
                int off = di_off[k];
                if (d & 1)
                    cp16(sd + (unsigned)(d ^ 1),
                         off >= 0 ? (const void*)(cb + off) : (const void*)cb,
                         off >= 0 ? 16 : 0);
                else
                    cp4(sd + (unsigned)d,
                        off >= 0 ? (const void*)(cb + off) : (const void*)cb,
                        off >= 0 ? 4 : 0);
            }
        }
        const float* wb = pk0 + (size_t)t * CHUNK_W;
        unsigned wd = sb_s[buf];
#pragma unroll
        for (int k = 0; k < NW; k++) {
            int i = tid + k * 256;
            if (NWOPS % 256 == 0 || i < NWOPS)
                cp16(wd + (unsigned)i * 16, wb + i * 4, 16);
        }
        cp_commit();
    };

    float acc[2][4][4];
#pragma unroll
    for (int m = 0; m < 2; m++)
#pragma unroll
        for (int nn = 0; nn < 4; nn++)
#pragma unroll
            for (int x = 0; x < 4; x++) acc[m][nn][x] = 0.0f;

    const int abase = g4 * PLANE + wid * 40 + g2 + 3;
    const int a2off = 4 * PLANE;

    stage(0, 0);

    for (int t = 0; t < NCH; t++) {
        int buf = t & 1;
        if (t + 1 < NCH) {
            stage(t + 1, buf ^ 1);
            asm volatile("cp.async.wait_group 1;\n" ::);
        } else {
            asm volatile("cp.async.wait_group 0;\n" ::);
        }
        __syncthreads();

        const float* sif = si[buf];
        const float* sbf = sb[buf];
#pragma unroll
        for (int r = 0; r < (ONEROW ? 1 : 3); r++) {
#pragma unroll
            for (int q = 0; q < 3; q++) {
                const int tap = r * 3 + q;
                uint b[4][2];
#pragma unroll
                for (int nn = 0; nn < 4; nn++) {
                    float2 v = *reinterpret_cast<const float2*>(
                        sbf + ((tap * 4 + nn) * 32 + lane) * 2);
                    b[nn][0] = __float_as_uint(v.x);
                    b[nn][1] = __float_as_uint(v.y);
                }
#pragma unroll
                for (int m = 0; m < 2; m++) {
                    int ai = abase + r * 40 + q + m * 16;
                    uint a0 = __float_as_uint(sif[ai]);
                    uint a1 = __float_as_uint(sif[ai + 8]);
                    uint a2 = __float_as_uint(sif[ai + a2off]);
                    uint a3 = __float_as_uint(sif[ai + a2off + 8]);
#pragma unroll
                    for (int nn = 0; nn < 4; nn++)
                        mma_tf32(acc[m][nn], a0, a1, a2, a3,
                                 b[nn][0], b[nn][1]);
                }
            }
        }
        __syncthreads();
    }

    // ---- epilogue ----
    if (POOL) {
        // Arena is dead now (trailing __syncthreads). Stash activated +
        // rounded values [h:8][w:32][oc:32 pad33], then pooled write.
#pragma unroll
        for (int m = 0; m < 2; m++)
#pragma unroll
            for (int nn = 0; nn < 4; nn++) {
                int ocl = nn * 8 + 2 * g4;
#pragma unroll
                for (int x = 0; x < 4; x++) {
                    int wl = m * 16 + g2 + ((x >> 1) ? 8 : 0);
                    sO[wid * (32 * 33) + wl * 33 + ocl + (x & 1)] =
                        tf32r(dlrelu(acc[m][nn][x]));
                }
            }
        __syncthreads();
        const int H2 = H >> 1, W2 = W >> 1;
        const int pw = tid & 15, ph = (tid >> 4) & 3, ob = tid >> 6;
#pragma unroll
        for (int k = 0; k < 8; k++) {
            int ocl = ob * 8 + k;
            const float* s0 = sO + (2 * ph) * (32 * 33) + (2 * pw) * 33 + ocl;
            float v = fmaxf(fmaxf(s0[0], s0[33]),
                            fmaxf(s0[32 * 33], s0[32 * 33 + 33]));
            out[((size_t)(n * Cout + ocg * 32 + ocl) * H2 + (h0 >> 1) + ph) * W2
                + (w0 >> 1) + pw] = v;
        }
    } else {
        const int h = h0 + wid;
#pragma unroll
        for (int m = 0; m < 2; m++) {
#pragma unroll
            for (int nn = 0; nn < 4; nn++) {
                int oc = ocg * 32 + nn * 8 + 2 * g4;
                int wv = w0 + m * 16 + g2;
                float* p0 = out + ((size_t)(n * Cout + oc) * H + h) * W + wv;
                float* p1 = p0 + (size_t)H * W;
                float v0 = dlrelu(acc[m][nn][0]);
                float v1 = dlrelu(acc[m][nn][1]);
                float v2 = dlrelu(acc[m][nn][2]);
                float v3 = dlrelu(acc[m][nn][3]);
                if (doRound) { v0 = tf32r(v0); v1 = tf32r(v1);
                               v2 = tf32r(v2); v3 = tf32r(v3); }
                p0[0] = v0; p1[0] = v1; p0[8] = v2; p1[8] = v3;
            }
        }
    }
}

// ---------------------------------------------------------------------------
extern "C" void kernel_launch(void* const* d_in, const int* in_sizes, int n_in,
                              void* d_out, int out_size)
{
    const float* x  = (const float*)d_in[0];
    const float* w1 = (const float*)d_in[1];
    const float* w2 = (const float*)d_in[2];
    const float* w3 = (const float*)d_in[3];
    const float* w4 = (const float*)d_in[4];
    const float* w5 = (const float*)d_in[5];
    const float* w6 = (const float*)d_in[6];
    float* out = (float*)d_out;

    float *A, *B, *Wp;
    cudaGetSymbolAddress((void**)&A, g_bufA);
    cudaGetSymbolAddress((void**)&B, g_bufB);
    cudaGetSymbolAddress((void**)&Wp, g_bufW);

    const int o2 = 0, o3 = 9216, o4 = 27648, o5 = 64512, o6 = 89088;

    // Prep: fused round + pack of all conv weights.
    pack_all<<<540, 256>>>(w2, w3, w4, w5, w6, Wp);

    // conv1: x [2,1,1024,256] -> A [2,32,1024,256]
    conv5x5_c1<<<dim3(4, 256, 2), 256>>>(x, w1, A);

    // conv2 (+pool1 fused): A -> B [2,32,512,128]
    conv3x3_mma<32, 0, 1><<<dim3(8, 128, 2), 256>>>(A, Wp + o2, B,
                                                    1024, 256, 512, 1, 1);

    // conv3: B -> A [2,64,512,128] (sliceH=32)
    conv3x3_mma<32, 0, 0><<<dim3(4, 64, 4), 256>>>(B, Wp + o3, A,
                                                   512, 128, 32, 2, 1);

    // conv4 (+pool2 fused): A -> B [2,64,256,64]
    conv3x3_mma<64, 0, 1><<<dim3(4, 64, 4), 256>>>(A, Wp + o4, B,
                                                   512, 128, 32, 2, 1);

    // conv5: B -> A [2,128,256,64] (1x3 middle row)
    conv3x3_mma<64, 1, 0><<<dim3(2, 32, 8), 256>>>(B, Wp + o5, A,
                                                   256, 64, 1, 4, 1);

    // conv6: A -> out (final: no rounding)
    conv3x3_mma<128, 1, 0><<<dim3(2, 32, 8), 256>>>(A, Wp + o6, out,
                                                    256, 64, 1, 4, 0);
}